// round 1
// baseline (speedup 1.0000x reference)
#include <cuda_runtime.h>

#define NN   20000
#define NE   640000
#define F    128
#define NRBF 20
#define C3   384
#define PI_OVER_5 0.6283185307179586f

// ---------------- scratch (__device__ globals; no allocation allowed) ------
__device__ int   g_is64;
__device__ int   g_cnt[NN];
__device__ int   g_cur[NN];
__device__ int   g_off[NN + 1];
__device__ int   g_order[NE];
__device__ float g_phi[(size_t)NN * C3];

// ---------------- index helper: nbrs may be int64 or int32 ----------------
__device__ __forceinline__ int nb_get(const void* nbrs, long long k) {
    if (g_is64) return (int)((const long long*)nbrs)[k];
    return ((const int*)nbrs)[k];
}

// Detect whether nbrs is int64 (values fit in [0, NN)) or int32.
__global__ void detect_kernel(const void* nbrs) {
    const long long* p = (const long long*)nbrs;
    int is64 = 1;
    for (int e = 0; e < 1000; e++) {
        long long a = p[2 * e], b = p[2 * e + 1];
        if (a < 0 || a >= NN || b < 0 || b >= NN) { is64 = 0; break; }
    }
    g_is64 = is64;
}

__global__ void zero_kernel() {
    int i = blockIdx.x * blockDim.x + threadIdx.x;
    if (i < NN) { g_cnt[i] = 0; g_cur[i] = 0; }
}

__global__ void hist_kernel(const void* nbrs) {
    int e = blockIdx.x * blockDim.x + threadIdx.x;
    if (e < NE) {
        int i = nb_get(nbrs, 2LL * e);
        atomicAdd(&g_cnt[i], 1);
    }
}

// Single-block inclusive scan over NN counts -> exclusive offsets.
__global__ void scan_kernel() {
    __shared__ int sh[1024];
    __shared__ int carry;
    const int tid = threadIdx.x;
    if (tid == 0) carry = 0;
    __syncthreads();
    for (int base = 0; base < NN; base += 1024) {
        int i = base + tid;
        int v = (i < NN) ? g_cnt[i] : 0;
        sh[tid] = v;
        __syncthreads();
        for (int s = 1; s < 1024; s <<= 1) {
            int t = (tid >= s) ? sh[tid - s] : 0;
            __syncthreads();
            sh[tid] += t;
            __syncthreads();
        }
        if (i < NN) g_off[i + 1] = carry + sh[tid];
        __syncthreads();
        if (tid == 1023) carry += sh[1023];
        __syncthreads();
    }
    if (tid == 0) g_off[0] = 0;
}

__global__ void bucket_kernel(const void* nbrs) {
    int e = blockIdx.x * blockDim.x + threadIdx.x;
    if (e < NE) {
        int i = nb_get(nbrs, 2LL * e);
        int p = atomicAdd(&g_cur[i], 1);
        g_order[g_off[i] + p] = e;
    }
}

// ---------------- node MLP: phi = silu(s@W1+b1)@W2 + b2 -------------------
// 32 nodes per block, 128 threads (thread = feature column).
__global__ __launch_bounds__(F) void node_mlp_kernel(
    const float* __restrict__ s,
    const float* __restrict__ W1, const float* __restrict__ b1,
    const float* __restrict__ W2, const float* __restrict__ b2)
{
    __shared__ float sh_s[32][F];
    __shared__ float sh_h[32][F];
    const int tid = threadIdx.x;
    const int n0 = blockIdx.x * 32;

    #pragma unroll
    for (int n = 0; n < 32; n++) {
        int node = n0 + n;
        sh_s[n][tid] = (node < NN) ? s[(size_t)node * F + tid] : 0.f;
    }
    __syncthreads();

    float bb = b1[tid];
    for (int gq = 0; gq < 32; gq += 8) {
        float acc[8];
        #pragma unroll
        for (int n = 0; n < 8; n++) acc[n] = bb;
        for (int k = 0; k < F; k++) {
            float w = W1[k * F + tid];
            #pragma unroll
            for (int n = 0; n < 8; n++) acc[n] += sh_s[gq + n][k] * w;
        }
        #pragma unroll
        for (int n = 0; n < 8; n++) {
            float x = acc[n];
            sh_h[gq + n][tid] = x * (1.f / (1.f + __expf(-x)));
        }
    }
    __syncthreads();

    float b20 = b2[tid], b21 = b2[tid + F], b22 = b2[tid + 2 * F];
    for (int gq = 0; gq < 32; gq += 8) {
        float a0[8], a1[8], a2[8];
        #pragma unroll
        for (int n = 0; n < 8; n++) { a0[n] = b20; a1[n] = b21; a2[n] = b22; }
        for (int k = 0; k < F; k++) {
            float w0 = W2[k * C3 + tid];
            float w1 = W2[k * C3 + F + tid];
            float w2 = W2[k * C3 + 2 * F + tid];
            #pragma unroll
            for (int n = 0; n < 8; n++) {
                float h = sh_h[gq + n][k];
                a0[n] += h * w0; a1[n] += h * w1; a2[n] += h * w2;
            }
        }
        #pragma unroll
        for (int n = 0; n < 8; n++) {
            int node = n0 + gq + n;
            if (node < NN) {
                size_t base = (size_t)node * C3;
                g_phi[base + tid]         = a0[n];
                g_phi[base + F + tid]     = a1[n];
                g_phi[base + 2 * F + tid] = a2[n];
            }
        }
    }
}

// ---------------- edge gather: atomic-free segment sum ---------------------
// One block per destination node; thread f owns feature f.
__global__ __launch_bounds__(F, 4) void gather_kernel(
    const float* __restrict__ vj,
    const float* __restrict__ rij,
    const void*  __restrict__ nbrs,
    const float* __restrict__ Wd,
    const float* __restrict__ bd,
    float* __restrict__ out_s,
    float* __restrict__ out_v)
{
    const int i = blockIdx.x;
    const int f = threadIdx.x;

    // Preload Wd columns for this thread's 3 output channels into registers.
    float wd0[NRBF], wd1[NRBF], wd2[NRBF];
    #pragma unroll
    for (int t = 0; t < NRBF; t++) {
        wd0[t] = Wd[t * C3 + f];
        wd1[t] = Wd[t * C3 + F + f];
        wd2[t] = Wd[t * C3 + 2 * F + f];
    }
    const float bd0 = bd[f], bd1 = bd[F + f], bd2 = bd[2 * F + f];

    float acc_s = 0.f, av0 = 0.f, av1 = 0.f, av2 = 0.f;

    __shared__ float se_g[NRBF];
    __shared__ float se_env, se_u0, se_u1, se_u2;
    __shared__ int   se_j;

    const int e0 = g_off[i];
    const int e1 = g_off[i + 1];

    for (int e = e0; e < e1; e++) {
        int idx = g_order[e];
        if (f == 0) {
            float r0 = rij[3 * (size_t)idx];
            float r1 = rij[3 * (size_t)idx + 1];
            float r2 = rij[3 * (size_t)idx + 2];
            float d2 = r0 * r0 + r1 * r1 + r2 * r2 + 3e-15f;
            float d  = sqrtf(d2);
            float invd = 1.f / d;
            se_u0 = r0 * invd; se_u1 = r1 * invd; se_u2 = r2 * invd;
            float x = d * PI_OVER_5;
            float s1, c1;
            __sincosf(x, &s1, &c1);
            float env = (d < 5.0f) ? 0.5f * (c1 + 1.f) : 0.f;
            se_env = env;
            float scale = env * invd;
            float sp = 0.f, sc = s1;
            float twoc = 2.f * c1;
            #pragma unroll
            for (int t = 0; t < NRBF; t++) {
                se_g[t] = sc * scale;
                float sn = twoc * sc - sp;
                sp = sc; sc = sn;
            }
            se_j = nb_get(nbrs, 2LL * idx + 1);
        }
        __syncthreads();

        const int   j   = se_j;
        const float env = se_env;
        float w0 = bd0 * env, w1 = bd1 * env, w2 = bd2 * env;
        #pragma unroll
        for (int t = 0; t < NRBF; t++) {
            float gt = se_g[t];
            w0 += gt * wd0[t];
            w1 += gt * wd1[t];
            w2 += gt * wd2[t];
        }
        const float* pj = g_phi + (size_t)j * C3;
        float inv0 = pj[f]         * w0;
        float inv1 = pj[F + f]     * w1;
        float inv2 = pj[2 * F + f] * w2;
        acc_s += inv1;

        const float* vp = vj + (size_t)j * C3 + 3 * f;
        av0 += inv2 * se_u0 + inv0 * vp[0];
        av1 += inv2 * se_u1 + inv0 * vp[1];
        av2 += inv2 * se_u2 + inv0 * vp[2];
        __syncthreads();
    }

    out_s[(size_t)i * F + f] = acc_s;
    float* ov = out_v + (size_t)i * C3 + 3 * f;
    ov[0] = av0; ov[1] = av1; ov[2] = av2;
}

// ---------------- launch ---------------------------------------------------
extern "C" void kernel_launch(void* const* d_in, const int* in_sizes, int n_in,
                              void* d_out, int out_size) {
    const float* s   = (const float*)d_in[0];
    const float* vj  = (const float*)d_in[1];
    const float* rij = (const float*)d_in[2];
    const void*  nb  = d_in[3];
    const float* W1  = (const float*)d_in[4];
    const float* b1  = (const float*)d_in[5];
    const float* W2  = (const float*)d_in[6];
    const float* b2  = (const float*)d_in[7];
    const float* Wd  = (const float*)d_in[8];
    const float* bd  = (const float*)d_in[9];

    float* out_s = (float*)d_out;
    float* out_v = out_s + (size_t)NN * F;

    detect_kernel<<<1, 1>>>(nb);
    zero_kernel<<<(NN + 255) / 256, 256>>>();
    node_mlp_kernel<<<(NN + 31) / 32, F>>>(s, W1, b1, W2, b2);
    hist_kernel<<<(NE + 255) / 256, 256>>>(nb);
    scan_kernel<<<1, 1024>>>();
    bucket_kernel<<<(NE + 255) / 256, 256>>>(nb);
    gather_kernel<<<NN, F>>>(vj, rij, nb, Wd, bd, out_s, out_v);
}

// round 2
// speedup vs baseline: 1.8887x; 1.8887x over previous
#include <cuda_runtime.h>

#define NN   20000
#define NE   640000
#define F    128
#define NRBF 20
#define C3   384
#define ESTRIDE 32            // floats per edge record (128 B)
#define PI_OVER_5 0.6283185307179586f

// ---------------- scratch (__device__ globals; no allocation allowed) ------
__device__ int   g_is64;
__device__ int   g_cnt[NN];
__device__ int   g_cur[NN];
__device__ int   g_off[NN + 1];
__device__ int   g_order[NE];
__device__ float g_phi[(size_t)NN * C3];
__device__ float g_edge[(size_t)NE * ESTRIDE];

// ---------------- index helper: nbrs may be int64 or int32 ----------------
__device__ __forceinline__ int nb_get(const void* nbrs, long long k) {
    if (g_is64) return (int)((const long long*)nbrs)[k];
    return ((const int*)nbrs)[k];
}

__global__ void detect_kernel(const void* nbrs) {
    const long long* p = (const long long*)nbrs;
    int is64 = 1;
    for (int e = 0; e < 1000; e++) {
        long long a = p[2 * e], b = p[2 * e + 1];
        if (a < 0 || a >= NN || b < 0 || b >= NN) { is64 = 0; break; }
    }
    g_is64 = is64;
}

__global__ void zero_kernel() {
    int i = blockIdx.x * blockDim.x + threadIdx.x;
    if (i < NN) { g_cnt[i] = 0; g_cur[i] = 0; }
}

__global__ void hist_kernel(const void* nbrs) {
    int e = blockIdx.x * blockDim.x + threadIdx.x;
    if (e < NE) {
        int i = nb_get(nbrs, 2LL * e);
        atomicAdd(&g_cnt[i], 1);
    }
}

// Single-block scan over NN counts -> exclusive offsets.
__global__ void scan_kernel() {
    __shared__ int sh[1024];
    __shared__ int carry;
    const int tid = threadIdx.x;
    if (tid == 0) carry = 0;
    __syncthreads();
    for (int base = 0; base < NN; base += 1024) {
        int i = base + tid;
        int v = (i < NN) ? g_cnt[i] : 0;
        sh[tid] = v;
        __syncthreads();
        for (int s = 1; s < 1024; s <<= 1) {
            int t = (tid >= s) ? sh[tid - s] : 0;
            __syncthreads();
            sh[tid] += t;
            __syncthreads();
        }
        if (i < NN) g_off[i + 1] = carry + sh[tid];
        __syncthreads();
        if (tid == 1023) carry += sh[1023];
        __syncthreads();
    }
    if (tid == 0) g_off[0] = 0;
}

__global__ void bucket_kernel(const void* nbrs) {
    int e = blockIdx.x * blockDim.x + threadIdx.x;
    if (e < NE) {
        int i = nb_get(nbrs, 2LL * e);
        int p = atomicAdd(&g_cur[i], 1);
        g_order[g_off[i] + p] = e;
    }
}

// ---------------- per-edge scalar precompute (CSR order) -------------------
// Record layout (floats): [0..19]=sin_t*env/d, [20]=env, [21..23]=unit,
// [24]=j (bit-cast int), [25..31]=pad.
__global__ void edge_pre_kernel(const float* __restrict__ rij,
                                const void* __restrict__ nbrs) {
    int p = blockIdx.x * blockDim.x + threadIdx.x;
    if (p >= NE) return;
    int idx = g_order[p];

    float r0 = rij[3 * (size_t)idx];
    float r1 = rij[3 * (size_t)idx + 1];
    float r2 = rij[3 * (size_t)idx + 2];
    float d2 = r0 * r0 + r1 * r1 + r2 * r2 + 3e-15f;
    float d  = sqrtf(d2);
    float invd = 1.f / d;

    float x = d * PI_OVER_5;
    float s1, c1;
    __sincosf(x, &s1, &c1);
    float env = (d < 5.0f) ? 0.5f * (c1 + 1.f) : 0.f;
    float scale = env * invd;

    float vals[28];
    float sp = 0.f, sc = s1;
    float twoc = 2.f * c1;
    #pragma unroll
    for (int t = 0; t < NRBF; t++) {
        vals[t] = sc * scale;
        float sn = twoc * sc - sp;
        sp = sc; sc = sn;
    }
    vals[20] = env;
    vals[21] = r0 * invd;
    vals[22] = r1 * invd;
    vals[23] = r2 * invd;
    int j = nb_get(nbrs, 2LL * idx + 1);
    vals[24] = __int_as_float(j);
    vals[25] = 0.f; vals[26] = 0.f; vals[27] = 0.f;

    float4* dst = (float4*)(g_edge + (size_t)p * ESTRIDE);
    #pragma unroll
    for (int q = 0; q < 7; q++)
        dst[q] = make_float4(vals[4 * q], vals[4 * q + 1],
                             vals[4 * q + 2], vals[4 * q + 3]);
    dst[7] = make_float4(0.f, 0.f, 0.f, 0.f);
}

// ---------------- node MLP: phi = silu(s@W1+b1)@W2 + b2 -------------------
__global__ __launch_bounds__(F) void node_mlp_kernel(
    const float* __restrict__ s,
    const float* __restrict__ W1, const float* __restrict__ b1,
    const float* __restrict__ W2, const float* __restrict__ b2)
{
    __shared__ float sh_s[32][F];
    __shared__ float sh_h[32][F];
    const int tid = threadIdx.x;
    const int n0 = blockIdx.x * 32;

    #pragma unroll
    for (int n = 0; n < 32; n++) {
        int node = n0 + n;
        sh_s[n][tid] = (node < NN) ? s[(size_t)node * F + tid] : 0.f;
    }
    __syncthreads();

    float bb = b1[tid];
    for (int gq = 0; gq < 32; gq += 8) {
        float acc[8];
        #pragma unroll
        for (int n = 0; n < 8; n++) acc[n] = bb;
        for (int k = 0; k < F; k++) {
            float w = W1[k * F + tid];
            #pragma unroll
            for (int n = 0; n < 8; n++) acc[n] += sh_s[gq + n][k] * w;
        }
        #pragma unroll
        for (int n = 0; n < 8; n++) {
            float x = acc[n];
            sh_h[gq + n][tid] = x * (1.f / (1.f + __expf(-x)));
        }
    }
    __syncthreads();

    float b20 = b2[tid], b21 = b2[tid + F], b22 = b2[tid + 2 * F];
    for (int gq = 0; gq < 32; gq += 8) {
        float a0[8], a1[8], a2[8];
        #pragma unroll
        for (int n = 0; n < 8; n++) { a0[n] = b20; a1[n] = b21; a2[n] = b22; }
        for (int k = 0; k < F; k++) {
            float w0 = W2[k * C3 + tid];
            float w1 = W2[k * C3 + F + tid];
            float w2 = W2[k * C3 + 2 * F + tid];
            #pragma unroll
            for (int n = 0; n < 8; n++) {
                float h = sh_h[gq + n][k];
                a0[n] += h * w0; a1[n] += h * w1; a2[n] += h * w2;
            }
        }
        #pragma unroll
        for (int n = 0; n < 8; n++) {
            int node = n0 + gq + n;
            if (node < NN) {
                size_t base = (size_t)node * C3;
                g_phi[base + tid]         = a0[n];
                g_phi[base + F + tid]     = a1[n];
                g_phi[base + 2 * F + tid] = a2[n];
            }
        }
    }
}

// ---------------- gather: atomic-free segment sum, batched -----------------
// One block per destination node; thread f owns feature f.
// Batches of 16 edges per barrier pair; edge records staged via float4.
#define EBATCH 16
__global__ __launch_bounds__(F, 5) void gather_kernel(
    const float* __restrict__ vj,
    const float* __restrict__ Wd,
    const float* __restrict__ bd,
    float* __restrict__ out_s,
    float* __restrict__ out_v)
{
    const int i = blockIdx.x;
    const int f = threadIdx.x;

    // wd[20] = bd (env term is basis value #20).
    float wd0[NRBF + 1], wd1[NRBF + 1], wd2[NRBF + 1];
    #pragma unroll
    for (int t = 0; t < NRBF; t++) {
        wd0[t] = Wd[t * C3 + f];
        wd1[t] = Wd[t * C3 + F + f];
        wd2[t] = Wd[t * C3 + 2 * F + f];
    }
    wd0[NRBF] = bd[f];
    wd1[NRBF] = bd[F + f];
    wd2[NRBF] = bd[2 * F + f];

    __shared__ float4 sh4[EBATCH * 8];

    float acc_s = 0.f, av0 = 0.f, av1 = 0.f, av2 = 0.f;

    const int e0 = g_off[i];
    const int e1 = g_off[i + 1];
    const float4* src4 = (const float4*)g_edge;

    for (int b = e0; b < e1; b += EBATCH) {
        const int nb  = min(EBATCH, e1 - b);
        const int tot = nb * 8;
        __syncthreads();
        if (f < tot) sh4[f] = src4[(size_t)b * 8 + f];
        __syncthreads();

        for (int k = 0; k < nb; k++) {
            const float4* e4 = &sh4[k * 8];
            float eg[28];
            #pragma unroll
            for (int q = 0; q < 7; q++) {
                float4 v = e4[q];
                eg[4 * q] = v.x; eg[4 * q + 1] = v.y;
                eg[4 * q + 2] = v.z; eg[4 * q + 3] = v.w;
            }
            float w0 = 0.f, w1 = 0.f, w2 = 0.f;
            #pragma unroll
            for (int t = 0; t <= NRBF; t++) {
                float g = eg[t];
                w0 += g * wd0[t];
                w1 += g * wd1[t];
                w2 += g * wd2[t];
            }
            const int j = __float_as_int(eg[24]);
            const float u0 = eg[21], u1 = eg[22], u2 = eg[23];

            const float* pj = g_phi + (size_t)j * C3;
            float inv0 = pj[f] * w0;
            acc_s     += pj[F + f] * w1;
            float inv2 = pj[2 * F + f] * w2;

            const float* vp = vj + (size_t)j * C3 + 3 * f;
            av0 += inv2 * u0 + inv0 * vp[0];
            av1 += inv2 * u1 + inv0 * vp[1];
            av2 += inv2 * u2 + inv0 * vp[2];
        }
    }

    out_s[(size_t)i * F + f] = acc_s;
    float* ov = out_v + (size_t)i * C3 + 3 * f;
    ov[0] = av0; ov[1] = av1; ov[2] = av2;
}

// ---------------- launch ---------------------------------------------------
extern "C" void kernel_launch(void* const* d_in, const int* in_sizes, int n_in,
                              void* d_out, int out_size) {
    const float* s   = (const float*)d_in[0];
    const float* vj  = (const float*)d_in[1];
    const float* rij = (const float*)d_in[2];
    const void*  nb  = d_in[3];
    const float* W1  = (const float*)d_in[4];
    const float* b1  = (const float*)d_in[5];
    const float* W2  = (const float*)d_in[6];
    const float* b2  = (const float*)d_in[7];
    const float* Wd  = (const float*)d_in[8];
    const float* bd  = (const float*)d_in[9];

    float* out_s = (float*)d_out;
    float* out_v = out_s + (size_t)NN * F;

    detect_kernel<<<1, 1>>>(nb);
    zero_kernel<<<(NN + 255) / 256, 256>>>();
    node_mlp_kernel<<<(NN + 31) / 32, F>>>(s, W1, b1, W2, b2);
    hist_kernel<<<(NE + 255) / 256, 256>>>(nb);
    scan_kernel<<<1, 1024>>>();
    bucket_kernel<<<(NE + 255) / 256, 256>>>(nb);
    edge_pre_kernel<<<(NE + 255) / 256, 256>>>(rij, nb);
    gather_kernel<<<NN, F>>>(vj, Wd, bd, out_s, out_v);
}

// round 3
// speedup vs baseline: 2.2605x; 1.1969x over previous
#include <cuda_runtime.h>

#define NN   20000
#define NE   640000
#define F    128
#define NRBF 20
#define C3   384
#define ESTRIDE 32            // floats per edge record (128 B)
#define PI_OVER_5 0.6283185307179586f

typedef unsigned long long u64;

// ---------------- f32x2 packed-FMA helpers (sm_100+) -----------------------
__device__ __forceinline__ u64 pack2(float lo, float hi) {
    u64 r; asm("mov.b64 %0, {%1, %2};" : "=l"(r) : "f"(lo), "f"(hi)); return r;
}
__device__ __forceinline__ void unpack2(u64 v, float& lo, float& hi) {
    asm("mov.b64 {%0, %1}, %2;" : "=f"(lo), "=f"(hi) : "l"(v));
}
__device__ __forceinline__ u64 fma2(u64 a, u64 b, u64 c) {
    u64 d; asm("fma.rn.f32x2 %0, %1, %2, %3;" : "=l"(d) : "l"(a), "l"(b), "l"(c));
    return d;
}

// ---------------- scratch (__device__ globals; no allocation allowed) ------
__device__ int   g_is64;
__device__ int   g_cnt[NN];
__device__ int   g_cur[NN];
__device__ int   g_off[NN + 1];
__device__ float g_phi[(size_t)NN * C3];
__device__ float g_edge[(size_t)NE * ESTRIDE];

// ---------------- index helper: nbrs may be int64 or int32 ----------------
__device__ __forceinline__ int nb_get(const void* nbrs, long long k) {
    if (g_is64) return (int)((const long long*)nbrs)[k];
    return ((const int*)nbrs)[k];
}

__global__ void detect_kernel(const void* nbrs) {
    const long long* p = (const long long*)nbrs;
    int is64 = 1;
    for (int e = 0; e < 1000; e++) {
        long long a = p[2 * e], b = p[2 * e + 1];
        if (a < 0 || a >= NN || b < 0 || b >= NN) { is64 = 0; break; }
    }
    g_is64 = is64;
}

__global__ void zero_kernel() {
    int i = blockIdx.x * blockDim.x + threadIdx.x;
    if (i < NN) { g_cnt[i] = 0; g_cur[i] = 0; }
}

__global__ void hist_kernel(const void* nbrs) {
    int e = blockIdx.x * blockDim.x + threadIdx.x;
    if (e < NE) {
        int i = nb_get(nbrs, 2LL * e);
        atomicAdd(&g_cnt[i], 1);
    }
}

// Single-block scan over NN counts -> exclusive offsets.
__global__ void scan_kernel() {
    __shared__ int sh[1024];
    __shared__ int carry;
    const int tid = threadIdx.x;
    if (tid == 0) carry = 0;
    __syncthreads();
    for (int base = 0; base < NN; base += 1024) {
        int i = base + tid;
        int v = (i < NN) ? g_cnt[i] : 0;
        sh[tid] = v;
        __syncthreads();
        for (int s = 1; s < 1024; s <<= 1) {
            int t = (tid >= s) ? sh[tid - s] : 0;
            __syncthreads();
            sh[tid] += t;
            __syncthreads();
        }
        if (i < NN) g_off[i + 1] = carry + sh[tid];
        __syncthreads();
        if (tid == 1023) carry += sh[1023];
        __syncthreads();
    }
    if (tid == 0) g_off[0] = 0;
}

// ---------------- bucket + per-edge precompute (fused) ---------------------
// Record layout (floats): [0..19]=sin_t*env/d, [20..23]=(u0,u1,u2,env),
// [24]=j (bit-cast int), [25..31]=pad.
__global__ void bucket_pre_kernel(const void* __restrict__ nbrs,
                                  const float* __restrict__ rij) {
    int e = blockIdx.x * blockDim.x + threadIdx.x;
    if (e >= NE) return;
    int i = nb_get(nbrs, 2LL * e);
    int j = nb_get(nbrs, 2LL * e + 1);
    int p = g_off[i] + atomicAdd(&g_cur[i], 1);

    float r0 = rij[3 * (size_t)e];
    float r1 = rij[3 * (size_t)e + 1];
    float r2 = rij[3 * (size_t)e + 2];
    float d2 = r0 * r0 + r1 * r1 + r2 * r2 + 3e-15f;
    float d  = sqrtf(d2);
    float invd = 1.f / d;

    float x = d * PI_OVER_5;
    float s1, c1;
    __sincosf(x, &s1, &c1);
    float env = (d < 5.0f) ? 0.5f * (c1 + 1.f) : 0.f;
    float scale = env * invd;

    float vals[28];
    float sp = 0.f, sc = s1;
    float twoc = 2.f * c1;
    #pragma unroll
    for (int t = 0; t < NRBF; t++) {
        vals[t] = sc * scale;
        float sn = twoc * sc - sp;
        sp = sc; sc = sn;
    }
    vals[20] = r0 * invd;
    vals[21] = r1 * invd;
    vals[22] = r2 * invd;
    vals[23] = env;
    vals[24] = __int_as_float(j);
    vals[25] = 0.f; vals[26] = 0.f; vals[27] = 0.f;

    float4* dst = (float4*)(g_edge + (size_t)p * ESTRIDE);
    #pragma unroll
    for (int q = 0; q < 7; q++)
        dst[q] = make_float4(vals[4 * q], vals[4 * q + 1],
                             vals[4 * q + 2], vals[4 * q + 3]);
    dst[7] = make_float4(0.f, 0.f, 0.f, 0.f);
}

// ---------------- node MLP: phi = silu(s@W1+b1)@W2 + b2 (f32x2) -----------
__global__ __launch_bounds__(F) void node_mlp_kernel(
    const float* __restrict__ s,
    const float* __restrict__ W1, const float* __restrict__ b1,
    const float* __restrict__ W2, const float* __restrict__ b2)
{
    __shared__ float sh_s[32][F];
    __shared__ float sh_h[32][F];
    const int tid = threadIdx.x;
    const int n0 = blockIdx.x * 32;

    #pragma unroll
    for (int n = 0; n < 32; n++) {
        int node = n0 + n;
        sh_s[n][tid] = (node < NN) ? s[(size_t)node * F + tid] : 0.f;
    }
    __syncthreads();

    const float bb = b1[tid];
    for (int gq = 0; gq < 32; gq += 8) {
        u64 acc2[8];
        #pragma unroll
        for (int n = 0; n < 8; n++) acc2[n] = 0ull;
        for (int k = 0; k < F; k += 2) {
            u64 w2 = pack2(W1[k * F + tid], W1[(k + 1) * F + tid]);
            #pragma unroll
            for (int n = 0; n < 8; n++) {
                u64 s2 = *(const u64*)&sh_s[gq + n][k];
                acc2[n] = fma2(s2, w2, acc2[n]);
            }
        }
        #pragma unroll
        for (int n = 0; n < 8; n++) {
            float lo, hi;
            unpack2(acc2[n], lo, hi);
            float v = lo + hi + bb;
            sh_h[gq + n][tid] = v * (1.f / (1.f + __expf(-v)));
        }
    }
    __syncthreads();

    const float b20 = b2[tid], b21 = b2[tid + F], b22 = b2[tid + 2 * F];
    for (int gq = 0; gq < 32; gq += 8) {
        u64 a0[8], a1[8], a2[8];
        #pragma unroll
        for (int n = 0; n < 8; n++) { a0[n] = 0ull; a1[n] = 0ull; a2[n] = 0ull; }
        for (int k = 0; k < F; k += 2) {
            u64 w20 = pack2(W2[k * C3 + tid],         W2[(k + 1) * C3 + tid]);
            u64 w21 = pack2(W2[k * C3 + F + tid],     W2[(k + 1) * C3 + F + tid]);
            u64 w22 = pack2(W2[k * C3 + 2 * F + tid], W2[(k + 1) * C3 + 2 * F + tid]);
            #pragma unroll
            for (int n = 0; n < 8; n++) {
                u64 h2 = *(const u64*)&sh_h[gq + n][k];
                a0[n] = fma2(h2, w20, a0[n]);
                a1[n] = fma2(h2, w21, a1[n]);
                a2[n] = fma2(h2, w22, a2[n]);
            }
        }
        #pragma unroll
        for (int n = 0; n < 8; n++) {
            int node = n0 + gq + n;
            if (node < NN) {
                float lo, hi;
                size_t base = (size_t)node * C3;
                unpack2(a0[n], lo, hi); g_phi[base + tid]         = lo + hi + b20;
                unpack2(a1[n], lo, hi); g_phi[base + F + tid]     = lo + hi + b21;
                unpack2(a2[n], lo, hi); g_phi[base + 2 * F + tid] = lo + hi + b22;
            }
        }
    }
}

// ---------------- gather: atomic-free segment sum, f32x2 dot ---------------
#define EBATCH 16
__global__ __launch_bounds__(F, 4) void gather_kernel(
    const float* __restrict__ vj,
    const float* __restrict__ Wd,
    const float* __restrict__ bd,
    float* __restrict__ out_s,
    float* __restrict__ out_v)
{
    const int i = blockIdx.x;
    const int f = threadIdx.x;

    // Packed Wd column pairs (t even/odd) per output channel; env term -> bd.
    u64 wd0p[NRBF / 2], wd1p[NRBF / 2], wd2p[NRBF / 2];
    #pragma unroll
    for (int t = 0; t < NRBF / 2; t++) {
        wd0p[t] = pack2(Wd[(2 * t) * C3 + f],         Wd[(2 * t + 1) * C3 + f]);
        wd1p[t] = pack2(Wd[(2 * t) * C3 + F + f],     Wd[(2 * t + 1) * C3 + F + f]);
        wd2p[t] = pack2(Wd[(2 * t) * C3 + 2 * F + f], Wd[(2 * t + 1) * C3 + 2 * F + f]);
    }
    const float wde0 = bd[f], wde1 = bd[F + f], wde2 = bd[2 * F + f];

    __shared__ float4 sh4[EBATCH * 8];

    float acc_s = 0.f, av0 = 0.f, av1 = 0.f, av2 = 0.f;

    const int e0 = g_off[i];
    const int e1 = g_off[i + 1];
    const float4* src4 = (const float4*)g_edge;

    for (int b = e0; b < e1; b += EBATCH) {
        const int nb  = min(EBATCH, e1 - b);
        const int tot = nb * 8;
        __syncthreads();
        if (f < tot) sh4[f] = src4[(size_t)b * 8 + f];
        __syncthreads();

        for (int k = 0; k < nb; k++) {
            const float* rec = (const float*)&sh4[k * 8];
            const u64*   bp  = (const u64*)rec;

            u64 w0p = 0ull, w1p = 0ull, w2p = 0ull;
            #pragma unroll
            for (int t = 0; t < NRBF / 2; t++) {
                u64 g2 = bp[t];
                w0p = fma2(g2, wd0p[t], w0p);
                w1p = fma2(g2, wd1p[t], w1p);
                w2p = fma2(g2, wd2p[t], w2p);
            }
            float4 quad = *(const float4*)(rec + 20);   // u0,u1,u2,env
            const float env = quad.w;
            float lo, hi;
            unpack2(w0p, lo, hi); float w0 = fmaf(env, wde0, lo + hi);
            unpack2(w1p, lo, hi); float w1 = fmaf(env, wde1, lo + hi);
            unpack2(w2p, lo, hi); float w2 = fmaf(env, wde2, lo + hi);

            const int j = __float_as_int(rec[24]);

            const float* pj = g_phi + (size_t)j * C3;
            float inv0 = pj[f] * w0;
            acc_s     += pj[F + f] * w1;
            float inv2 = pj[2 * F + f] * w2;

            const float* vp = vj + (size_t)j * C3 + 3 * f;
            av0 += inv2 * quad.x + inv0 * vp[0];
            av1 += inv2 * quad.y + inv0 * vp[1];
            av2 += inv2 * quad.z + inv0 * vp[2];
        }
    }

    out_s[(size_t)i * F + f] = acc_s;
    float* ov = out_v + (size_t)i * C3 + 3 * f;
    ov[0] = av0; ov[1] = av1; ov[2] = av2;
}

// ---------------- launch ---------------------------------------------------
extern "C" void kernel_launch(void* const* d_in, const int* in_sizes, int n_in,
                              void* d_out, int out_size) {
    const float* s   = (const float*)d_in[0];
    const float* vj  = (const float*)d_in[1];
    const float* rij = (const float*)d_in[2];
    const void*  nb  = d_in[3];
    const float* W1  = (const float*)d_in[4];
    const float* b1  = (const float*)d_in[5];
    const float* W2  = (const float*)d_in[6];
    const float* b2  = (const float*)d_in[7];
    const float* Wd  = (const float*)d_in[8];
    const float* bd  = (const float*)d_in[9];

    float* out_s = (float*)d_out;
    float* out_v = out_s + (size_t)NN * F;

    detect_kernel<<<1, 1>>>(nb);
    zero_kernel<<<(NN + 255) / 256, 256>>>();
    node_mlp_kernel<<<(NN + 31) / 32, F>>>(s, W1, b1, W2, b2);
    hist_kernel<<<(NE + 255) / 256, 256>>>(nb);
    scan_kernel<<<1, 1024>>>();
    bucket_pre_kernel<<<(NE + 255) / 256, 256>>>(nb, rij);
    gather_kernel<<<NN, F>>>(vj, Wd, bd, out_s, out_v);
}

// round 5
// speedup vs baseline: 2.3887x; 1.0567x over previous
#include <cuda_runtime.h>

#define NN   20000
#define NE   640000
#define F    128
#define NRBF 20
#define C3   384
#define ESTRIDE 32            // floats per edge record (128 B)
#define EBATCH 16
#define PI_OVER_5 0.6283185307179586f

typedef unsigned long long u64;

// ---------------- f32x2 packed-FMA helpers (sm_100+) -----------------------
__device__ __forceinline__ u64 pack2(float lo, float hi) {
    u64 r; asm("mov.b64 %0, {%1, %2};" : "=l"(r) : "f"(lo), "f"(hi)); return r;
}
__device__ __forceinline__ void unpack2(u64 v, float& lo, float& hi) {
    asm("mov.b64 {%0, %1}, %2;" : "=f"(lo), "=f"(hi) : "l"(v));
}
__device__ __forceinline__ u64 fma2(u64 a, u64 b, u64 c) {
    u64 d; asm("fma.rn.f32x2 %0, %1, %2, %3;" : "=l"(d) : "l"(a), "l"(b), "l"(c));
    return d;
}

// ---------------- scratch (__device__ globals; no allocation allowed) ------
__device__ int    g_is64;
__device__ int    g_cnt[NN];
__device__ int    g_cur[NN];
__device__ int    g_off[NN + 1];
__device__ float4 g_phiT[(size_t)NN * F];     // (phi0, phi1, phi2, pad) per (node,f)
__device__ float  g_edge[(size_t)NE * ESTRIDE];

// ---------------- index helper: nbrs may be int64 or int32 ----------------
__device__ __forceinline__ int nb_get(const void* nbrs, long long k) {
    if (g_is64) return (int)((const long long*)nbrs)[k];
    return ((const int*)nbrs)[k];
}

// Parallel detection: treat first 1024 pairs as int64; if any out of range,
// the data must be int32.
__global__ void detect_kernel(const void* nbrs) {
    __shared__ int bad;
    if (threadIdx.x == 0) bad = 0;
    __syncthreads();
    const long long* p = (const long long*)nbrs;
    int mybad = 0;
    for (int e = threadIdx.x; e < 1024; e += 256) {
        long long a = p[2 * e], b = p[2 * e + 1];
        if (a < 0 || a >= NN || b < 0 || b >= NN) mybad = 1;
    }
    if (mybad) atomicOr(&bad, 1);
    __syncthreads();
    if (threadIdx.x == 0) g_is64 = !bad;
}

__global__ void zero_kernel() {
    int i = blockIdx.x * blockDim.x + threadIdx.x;
    if (i < NN) { g_cnt[i] = 0; g_cur[i] = 0; }
}

__global__ void hist_kernel(const void* nbrs) {
    int e = blockIdx.x * blockDim.x + threadIdx.x;
    if (e < NE) {
        int i = nb_get(nbrs, 2LL * e);
        atomicAdd(&g_cnt[i], 1);
    }
}

// Single-block scan over NN counts -> exclusive offsets.
__global__ void scan_kernel() {
    __shared__ int sh[1024];
    __shared__ int carry;
    const int tid = threadIdx.x;
    if (tid == 0) carry = 0;
    __syncthreads();
    for (int base = 0; base < NN; base += 1024) {
        int i = base + tid;
        int v = (i < NN) ? g_cnt[i] : 0;
        sh[tid] = v;
        __syncthreads();
        for (int s = 1; s < 1024; s <<= 1) {
            int t = (tid >= s) ? sh[tid - s] : 0;
            __syncthreads();
            sh[tid] += t;
            __syncthreads();
        }
        if (i < NN) g_off[i + 1] = carry + sh[tid];
        __syncthreads();
        if (tid == 1023) carry += sh[1023];
        __syncthreads();
    }
    if (tid == 0) g_off[0] = 0;
}

// ---------------- bucket + per-edge precompute (fused) ---------------------
// Record layout (floats): [0..19]=sin_t*env/d, [20]=env, [21..23]=pad,
// [24..26]=unit, [27]=j (bit-cast), [28..31]=pad.
__global__ void bucket_pre_kernel(const void* __restrict__ nbrs,
                                  const float* __restrict__ rij) {
    int e = blockIdx.x * blockDim.x + threadIdx.x;
    if (e >= NE) return;
    int i = nb_get(nbrs, 2LL * e);
    int j = nb_get(nbrs, 2LL * e + 1);
    int p = g_off[i] + atomicAdd(&g_cur[i], 1);

    float r0 = rij[3 * (size_t)e];
    float r1 = rij[3 * (size_t)e + 1];
    float r2 = rij[3 * (size_t)e + 2];
    float d2 = r0 * r0 + r1 * r1 + r2 * r2 + 3e-15f;
    float d  = sqrtf(d2);
    float invd = 1.f / d;

    float x = d * PI_OVER_5;
    float s1, c1;
    __sincosf(x, &s1, &c1);
    float env = (d < 5.0f) ? 0.5f * (c1 + 1.f) : 0.f;
    float scale = env * invd;

    float vals[32];
    float sp = 0.f, sc = s1;
    float twoc = 2.f * c1;
    #pragma unroll
    for (int t = 0; t < NRBF; t++) {
        vals[t] = sc * scale;
        float sn = twoc * sc - sp;
        sp = sc; sc = sn;
    }
    vals[20] = env;
    vals[21] = 0.f; vals[22] = 0.f; vals[23] = 0.f;
    vals[24] = r0 * invd;
    vals[25] = r1 * invd;
    vals[26] = r2 * invd;
    vals[27] = __int_as_float(j);
    vals[28] = 0.f; vals[29] = 0.f; vals[30] = 0.f; vals[31] = 0.f;

    float4* dst = (float4*)(g_edge + (size_t)p * ESTRIDE);
    #pragma unroll
    for (int q = 0; q < 8; q++)
        __stcs(dst + q, make_float4(vals[4 * q], vals[4 * q + 1],
                                    vals[4 * q + 2], vals[4 * q + 3]));
}

// ---------------- node MLP: phiT = silu(s@W1+b1)@W2 + b2 (f32x2) ----------
__global__ __launch_bounds__(F) void node_mlp_kernel(
    const float* __restrict__ s,
    const float* __restrict__ W1, const float* __restrict__ b1,
    const float* __restrict__ W2, const float* __restrict__ b2)
{
    __shared__ float sh_s[32][F];
    __shared__ float sh_h[32][F];
    const int tid = threadIdx.x;
    const int n0 = blockIdx.x * 32;

    #pragma unroll
    for (int n = 0; n < 32; n++) {
        int node = n0 + n;
        sh_s[n][tid] = (node < NN) ? s[(size_t)node * F + tid] : 0.f;
    }
    __syncthreads();

    const float bb = b1[tid];
    for (int gq = 0; gq < 32; gq += 8) {
        u64 acc2[8];
        #pragma unroll
        for (int n = 0; n < 8; n++) acc2[n] = 0ull;
        for (int k = 0; k < F; k += 2) {
            u64 w2 = pack2(W1[k * F + tid], W1[(k + 1) * F + tid]);
            #pragma unroll
            for (int n = 0; n < 8; n++) {
                u64 s2 = *(const u64*)&sh_s[gq + n][k];
                acc2[n] = fma2(s2, w2, acc2[n]);
            }
        }
        #pragma unroll
        for (int n = 0; n < 8; n++) {
            float lo, hi;
            unpack2(acc2[n], lo, hi);
            float v = lo + hi + bb;
            sh_h[gq + n][tid] = v * (1.f / (1.f + __expf(-v)));
        }
    }
    __syncthreads();

    const float b20 = b2[tid], b21 = b2[tid + F], b22 = b2[tid + 2 * F];
    for (int gq = 0; gq < 32; gq += 8) {
        u64 a0[8], a1[8], a2[8];
        #pragma unroll
        for (int n = 0; n < 8; n++) { a0[n] = 0ull; a1[n] = 0ull; a2[n] = 0ull; }
        for (int k = 0; k < F; k += 2) {
            u64 w20 = pack2(W2[k * C3 + tid],         W2[(k + 1) * C3 + tid]);
            u64 w21 = pack2(W2[k * C3 + F + tid],     W2[(k + 1) * C3 + F + tid]);
            u64 w22 = pack2(W2[k * C3 + 2 * F + tid], W2[(k + 1) * C3 + 2 * F + tid]);
            #pragma unroll
            for (int n = 0; n < 8; n++) {
                u64 h2 = *(const u64*)&sh_h[gq + n][k];
                a0[n] = fma2(h2, w20, a0[n]);
                a1[n] = fma2(h2, w21, a1[n]);
                a2[n] = fma2(h2, w22, a2[n]);
            }
        }
        #pragma unroll
        for (int n = 0; n < 8; n++) {
            int node = n0 + gq + n;
            if (node < NN) {
                float l0, h0, l1, h1, l2, h2v;
                unpack2(a0[n], l0, h0);
                unpack2(a1[n], l1, h1);
                unpack2(a2[n], l2, h2v);
                g_phiT[(size_t)node * F + tid] =
                    make_float4(l0 + h0 + b20, l1 + h1 + b21, l2 + h2v + b22, 0.f);
            }
        }
    }
}

// ---------------- gather: atomic-free segment sum ---------------------------
__device__ __forceinline__ void gather_body(
    const float* rec, const u64* bp,
    const u64* wd0p, const u64* wd1p, const u64* wd2p,
    float wde0, float wde1, float wde2,
    const float* __restrict__ vj, const float4* __restrict__ phiT, int f,
    float& acc_s, float& av0, float& av1, float& av2)
{
    u64 w0p = 0ull, w1p = 0ull, w2p = 0ull;
    #pragma unroll
    for (int t = 0; t < NRBF / 2; t++) {
        u64 g2 = bp[t];
        w0p = fma2(g2, wd0p[t], w0p);
        w1p = fma2(g2, wd1p[t], w1p);
        w2p = fma2(g2, wd2p[t], w2p);
    }
    const float env = rec[20];
    float4 uj = *(const float4*)(rec + 24);   // u0,u1,u2,jbits
    const int j = __float_as_int(uj.w);

    float lo, hi;
    unpack2(w0p, lo, hi); float w0 = fmaf(env, wde0, lo + hi);
    unpack2(w1p, lo, hi); float w1 = fmaf(env, wde1, lo + hi);
    unpack2(w2p, lo, hi); float w2 = fmaf(env, wde2, lo + hi);

    float4 ph = phiT[(size_t)j * F + f];
    const float* vp = vj + (size_t)j * C3 + 3 * f;
    float va = vp[0], vb = vp[1], vc = vp[2];

    float inv0 = ph.x * w0;
    acc_s     += ph.y * w1;
    float inv2 = ph.z * w2;

    av0 += inv2 * uj.x + inv0 * va;
    av1 += inv2 * uj.y + inv0 * vb;
    av2 += inv2 * uj.z + inv0 * vc;
}

__global__ __launch_bounds__(F, 4) void gather_kernel(
    const float* __restrict__ vj,
    const float* __restrict__ Wd,
    const float* __restrict__ bd,
    float* __restrict__ out_s,
    float* __restrict__ out_v)
{
    const int i = blockIdx.x;
    const int f = threadIdx.x;

    u64 wd0p[NRBF / 2], wd1p[NRBF / 2], wd2p[NRBF / 2];
    #pragma unroll
    for (int t = 0; t < NRBF / 2; t++) {
        wd0p[t] = pack2(Wd[(2 * t) * C3 + f],         Wd[(2 * t + 1) * C3 + f]);
        wd1p[t] = pack2(Wd[(2 * t) * C3 + F + f],     Wd[(2 * t + 1) * C3 + F + f]);
        wd2p[t] = pack2(Wd[(2 * t) * C3 + 2 * F + f], Wd[(2 * t + 1) * C3 + 2 * F + f]);
    }
    const float wde0 = bd[f], wde1 = bd[F + f], wde2 = bd[2 * F + f];

    __shared__ float4 sh4[EBATCH * 8];

    float acc_s = 0.f, av0 = 0.f, av1 = 0.f, av2 = 0.f;

    const int e0 = g_off[i];
    const int e1 = g_off[i + 1];
    const float4* src4 = (const float4*)g_edge;
    const float4* phiT = g_phiT;

    for (int b = e0; b < e1; b += EBATCH) {
        const int nb = min(EBATCH, e1 - b);
        __syncthreads();
        if (f < nb * 8) sh4[f] = __ldcs(src4 + (size_t)b * 8 + f);
        __syncthreads();

        if (nb == EBATCH) {
            #pragma unroll 4
            for (int k = 0; k < EBATCH; k++) {
                const float* rec = (const float*)&sh4[k * 8];
                gather_body(rec, (const u64*)rec, wd0p, wd1p, wd2p,
                            wde0, wde1, wde2, vj, phiT, f,
                            acc_s, av0, av1, av2);
            }
        } else {
            for (int k = 0; k < nb; k++) {
                const float* rec = (const float*)&sh4[k * 8];
                gather_body(rec, (const u64*)rec, wd0p, wd1p, wd2p,
                            wde0, wde1, wde2, vj, phiT, f,
                            acc_s, av0, av1, av2);
            }
        }
    }

    __stcs(out_s + (size_t)i * F + f, acc_s);
    float* ov = out_v + (size_t)i * C3 + 3 * f;
    __stcs(ov + 0, av0);
    __stcs(ov + 1, av1);
    __stcs(ov + 2, av2);
}

// ---------------- launch ---------------------------------------------------
extern "C" void kernel_launch(void* const* d_in, const int* in_sizes, int n_in,
                              void* d_out, int out_size) {
    const float* s   = (const float*)d_in[0];
    const float* vj  = (const float*)d_in[1];
    const float* rij = (const float*)d_in[2];
    const void*  nb  = d_in[3];
    const float* W1  = (const float*)d_in[4];
    const float* b1  = (const float*)d_in[5];
    const float* W2  = (const float*)d_in[6];
    const float* b2  = (const float*)d_in[7];
    const float* Wd  = (const float*)d_in[8];
    const float* bd  = (const float*)d_in[9];

    float* out_s = (float*)d_out;
    float* out_v = out_s + (size_t)NN * F;

    detect_kernel<<<1, 256>>>(nb);
    zero_kernel<<<(NN + 255) / 256, 256>>>();
    node_mlp_kernel<<<(NN + 31) / 32, F>>>(s, W1, b1, W2, b2);
    hist_kernel<<<(NE + 255) / 256, 256>>>(nb);
    scan_kernel<<<1, 1024>>>();
    bucket_pre_kernel<<<(NE + 255) / 256, 256>>>(nb, rij);
    gather_kernel<<<NN, F>>>(vj, Wd, bd, out_s, out_v);
}